// round 17
// baseline (speedup 1.0000x reference)
#include <cuda_runtime.h>

#define VOCAB 32000
#define BATCH 4
#define SEQ   2048
#define NVEC  (VOCAB / 4)   // 8000 float4 per row
#define NOUT4 ((BATCH * VOCAB) / 4)   // 32000 float4 of output
#define TOTAL (BATCH * SEQ)           // 8192 rows
#define SCTA  256                     // scatter CTAs
#define STHR  32                      // scatter threads per CTA (256*32 = TOTAL)

// Scratch state. g_hist is zero at module load; the scatter kernel resets
// every dirtied entry (idempotent duplicate stores), so every launch sees a
// zero histogram. g_list needs no init/reset: argmax overwrites all TOTAL
// entries before scatter reads them.
__device__ int g_hist[BATCH * VOCAB];
__device__ int g_list[TOTAL];   // per-row (b << 16) | bidx (duplicates OK)

// One CTA per (b, s) row. Writes this CTA's 4-float4 slice of zeros to `out`
// (zeros are correct for untouched buckets and special tokens; touched
// buckets are overwritten by the scatter kernel), then argmax + hist add +
// plain store of the packed winner into g_list[row].
__global__ __launch_bounds__(256, 8)
void argmax_hist_kernel(const float* __restrict__ logits,
                        float* __restrict__ out) {
    const int row = blockIdx.x;                       // 0 .. B*S-1
    const float4* __restrict__ p =
        reinterpret_cast<const float4*>(logits + (size_t)row * VOCAB);
    const int tid = threadIdx.x;

    // Baseline zeros: 8192 CTAs x 4 float4 covers all outputs (guard tail).
    if (tid < 4) {
        const int oi = (row << 2) + tid;
        if (oi < NOUT4)
            reinterpret_cast<float4*>(out)[oi] = make_float4(0.f, 0.f, 0.f, 0.f);
    }

    float best = -3.402823466e+38f;
    int   bidx = 0;

    // Strided float4 scan, streaming (evict-first) loads. Strict '>' keeps
    // the first (lowest-index) max within a thread, matching jnp.argmax.
    #pragma unroll 4
    for (int i = tid; i < NVEC; i += 256) {
        float4 v = __ldcs(p + i);
        int base = i << 2;
        if (v.x > best) { best = v.x; bidx = base;     }
        if (v.y > best) { best = v.y; bidx = base + 1; }
        if (v.z > best) { best = v.z; bidx = base + 2; }
        if (v.w > best) { best = v.w; bidx = base + 3; }
    }

    // Warp reduction (tie -> smaller index)
    #pragma unroll
    for (int off = 16; off > 0; off >>= 1) {
        float ov = __shfl_down_sync(0xFFFFFFFFu, best, off);
        int   oi = __shfl_down_sync(0xFFFFFFFFu, bidx, off);
        if (ov > best || (ov == best && oi < bidx)) { best = ov; bidx = oi; }
    }

    __shared__ float s_val[8];
    __shared__ int   s_idx[8];
    const int wid = tid >> 5;
    const int lid = tid & 31;
    if (lid == 0) { s_val[wid] = best; s_idx[wid] = bidx; }
    __syncthreads();

    if (wid == 0) {
        best = (lid < 8) ? s_val[lid] : -3.402823466e+38f;
        bidx = (lid < 8) ? s_idx[lid] : 0x7FFFFFFF;
        #pragma unroll
        for (int off = 4; off > 0; off >>= 1) {
            float ov = __shfl_down_sync(0xFFFFFFFFu, best, off);
            int   oi = __shfl_down_sync(0xFFFFFFFFu, bidx, off);
            if (ov > best || (ov == best && oi < bidx)) { best = ov; bidx = oi; }
        }
        if (lid == 0) {
            const int b = row / SEQ;
            atomicAdd(&g_hist[b * VOCAB + bidx], 1);
            g_list[row] = (b << 16) | bidx;   // packed, no counter, no modulo
        }
    }
}

// Scatter: exactly TOTAL threads, one list entry each. Duplicate entries all
// read the SAME final count (this kernel runs after argmax completes); the
// one that sees c!=0 writes the final value and resets the hist entry; any
// duplicate that sees c==0 does nothing (the value already carries).
// Deterministic: final out depends only on final counts.
__global__ __launch_bounds__(STHR)
void scatter_kernel(float* __restrict__ out) {
    const int i = blockIdx.x * STHR + threadIdx.x;    // 0 .. TOTAL-1
    const int packed = __ldcg(&g_list[i]);
    const int bidx   = packed & 0xFFFF;
    const int bucket = (packed >> 16) * VOCAB + bidx;
    const int c = __ldcg(&g_hist[bucket]);
    if (c != 0) {
        g_hist[bucket] = 0;              // reset for next replay (idempotent)
        if (bidx > 2)                    // PAD=0, START=1, END=2 stay 0
            out[bucket] = fminf((float)c, 4.0f) * 0.25f;
    }
}

extern "C" void kernel_launch(void* const* d_in, const int* in_sizes, int n_in,
                              void* d_out, int out_size) {
    const float* logits = (const float*)d_in[0];
    float* out = (float*)d_out;

    argmax_hist_kernel<<<TOTAL, 256>>>(logits, out);
    scatter_kernel<<<SCTA, STHR>>>(out);
}